// round 1
// baseline (speedup 1.0000x reference)
#include <cuda_runtime.h>

#define FULL_MASK 0xFFFFFFFFu

// Problem constants
// B=8, H=256, W=256, K=8, C=64, N=B*H*W=524288
// R_NDC = 1.5/256*2 = 3/256; R_NDC^2 = 9/65536 (exact in binary)
__global__ __launch_bounds__(256) void rast_blend_kernel(
    const float* __restrict__ dist,
    const float* __restrict__ zbuf,
    const int*   __restrict__ pidx,
    const float* __restrict__ feat,
    float*       __restrict__ out)
{
    constexpr int C = 64;
    constexpr int K = 8;
    constexpr float INV_R2 = 65536.0f / 9.0f;

    __shared__ float s[C * 33];   // [channel][pixel-in-tile], pad 33 for conflict-free readout

    const int tid = threadIdx.x;
    const int wp  = tid >> 5;     // warp id 0..7
    const int l   = tid & 31;     // lane

    const int tileBase = blockIdx.x * 32;     // first pixel (linear over B*H*W) of this tile
    const int warpPix  = tileBase + wp * 4;   // this warp handles 4 consecutive pixels

    // ---- header: 4 pixels x K=8 = 32 contiguous entries, one coalesced load each ----
    const long hdr = (long)warpPix * K + l;
    float d  = __ldcs(dist + hdr);
    float z  = __ldcs(zbuf + hdr);
    int   id = __ldcs(pidx + hdr);

    float a = 1.0f - sqrtf(fminf(fmaxf(d * INV_R2, 0.001f), 1.0f));
    bool valid = (z >= 0.0f) && (id >= 0);
    a  = valid ? a : 0.0f;
    id = (id < 0) ? 0 : id;       // safe gather index (weight already zeroed)

    const float2* __restrict__ f2 = reinterpret_cast<const float2*>(feat);

    #pragma unroll
    for (int p = 0; p < 4; ++p) {
        float T  = 1.0f;          // transmittance prod_{j<k}(1-a_j)
        float ax = 0.0f, ay = 0.0f;
        #pragma unroll
        for (int k = 0; k < K; ++k) {
            float ak = __shfl_sync(FULL_MASK, a,  p * 8 + k);
            int   ik = __shfl_sync(FULL_MASK, id, p * 8 + k);
            float wk = ak * T;
            T *= (1.0f - ak);
            // coalesced gather: 32 lanes read the full 256B feature row
            float2 f = f2[(long)ik * 32 + l];
            ax = fmaf(wk, f.x, ax);
            ay = fmaf(wk, f.y, ay);
        }
        const int col = wp * 4 + p;
        s[(2 * l)     * 33 + col] = ax;
        s[(2 * l + 1) * 33 + col] = ay;
    }
    __syncthreads();

    // ---- coalesced transposed writeout: out[b][c][h][w0..w0+31] ----
    const int b  = tileBase >> 16;        // / (H*W)
    const int hw = tileBase & 65535;
    const int h  = hw >> 8;
    const int w0 = hw & 255;              // multiple of 32
    float* obase = out + ((long)b * C) * 65536 + (long)h * 256 + w0;

    #pragma unroll
    for (int it = 0; it < 8; ++it) {
        const int c = it * 8 + wp;
        __stcs(obase + (long)c * 65536 + l, s[c * 33 + l]);
    }
}

extern "C" void kernel_launch(void* const* d_in, const int* in_sizes, int n_in,
                              void* d_out, int out_size) {
    const float* dist = (const float*)d_in[0];
    const float* zbuf = (const float*)d_in[1];
    const int*   pidx = (const int*)d_in[2];
    const float* feat = (const float*)d_in[3];
    float* out = (float*)d_out;

    const int nPix = 8 * 256 * 256;       // 524288
    rast_blend_kernel<<<nPix / 32, 256>>>(dist, zbuf, pidx, feat, out);
}

// round 3
// speedup vs baseline: 1.0231x; 1.0231x over previous
#include <cuda_runtime.h>

#define FULL_MASK 0xFFFFFFFFu

// Feature-row gather with L2 evict_last priority via cache-policy register
// (bare .L2::evict_last qualifier is v8.b32-only on sm_103a ptxas; the
// createpolicy + .L2::cache_hint form works at any width).
__device__ __forceinline__ unsigned long long mk_evict_last_policy() {
    unsigned long long pol;
    asm volatile("createpolicy.fractional.L2::evict_last.b64 %0, 1.0;" : "=l"(pol));
    return pol;
}

__device__ __forceinline__ float2 ldg_feat(const float2* p, unsigned long long pol) {
    float2 v;
    asm volatile("ld.global.nc.L2::cache_hint.v2.f32 {%0,%1}, [%2], %3;"
                 : "=f"(v.x), "=f"(v.y) : "l"(p), "l"(pol));
    return v;
}

// Problem constants
// B=8, H=256, W=256, K=8, C=64, N=B*H*W=524288
// R_NDC = 1.5/256*2 = 3/256; R_NDC^2 = 9/65536 (exact in binary)
__global__ __launch_bounds__(256) void rast_blend_kernel(
    const float* __restrict__ dist,
    const float* __restrict__ zbuf,
    const int*   __restrict__ pidx,
    const float* __restrict__ feat,
    float*       __restrict__ out)
{
    constexpr int C = 64;
    constexpr int K = 8;
    constexpr float INV_R2 = 65536.0f / 9.0f;

    __shared__ float s[C * 33];   // [channel][pixel-in-tile], pad 33 for conflict-free readout

    const int tid = threadIdx.x;
    const int wp  = tid >> 5;     // warp id 0..7
    const int l   = tid & 31;     // lane

    const int tileBase = blockIdx.x * 32;     // first pixel (linear over B*H*W) of this tile
    const int warpPix  = tileBase + wp * 4;   // this warp handles 4 consecutive pixels

    // ---- header: 4 pixels x K=8 = 32 contiguous entries, one coalesced load each ----
    const long hdr = (long)warpPix * K + l;
    float d  = __ldcs(dist + hdr);
    float z  = __ldcs(zbuf + hdr);
    int   id = __ldcs(pidx + hdr);

    float a = 1.0f - sqrtf(fminf(fmaxf(d * INV_R2, 0.001f), 1.0f));
    bool valid = (z >= 0.0f) && (id >= 0);
    a  = valid ? a : 0.0f;
    id = (id < 0) ? 0 : id;       // safe gather index (weight already zeroed)

    const float2* __restrict__ f2 = reinterpret_cast<const float2*>(feat);
    const unsigned long long pol = mk_evict_last_policy();

    #pragma unroll
    for (int p = 0; p < 4; ++p) {
        float T  = 1.0f;          // transmittance prod_{j<k}(1-a_j)
        float ax = 0.0f, ay = 0.0f;
        #pragma unroll
        for (int k = 0; k < K; ++k) {
            float ak = __shfl_sync(FULL_MASK, a,  p * 8 + k);
            int   ik = __shfl_sync(FULL_MASK, id, p * 8 + k);
            // warp-uniform skip: ~14% of slots are empty (idx<0 or z<0) -> a_k == 0.
            // T never reaches exactly 0 (a_k <= 1 - sqrt(0.001)), so wk==0 iff ak==0.
            if (ak != 0.0f) {
                float wk = ak * T;
                // coalesced gather: 32 lanes read the full 256B feature row
                float2 f = ldg_feat(f2 + (long)ik * 32 + l, pol);
                ax = fmaf(wk, f.x, ax);
                ay = fmaf(wk, f.y, ay);
            }
            T *= (1.0f - ak);
        }
        const int col = wp * 4 + p;
        s[(2 * l)     * 33 + col] = ax;
        s[(2 * l + 1) * 33 + col] = ay;
    }
    __syncthreads();

    // ---- coalesced transposed writeout: out[b][c][h][w0..w0+31] ----
    const int b  = tileBase >> 16;        // / (H*W)
    const int hw = tileBase & 65535;
    const int h  = hw >> 8;
    const int w0 = hw & 255;              // multiple of 32
    float* obase = out + ((long)b * C) * 65536 + (long)h * 256 + w0;

    #pragma unroll
    for (int it = 0; it < 8; ++it) {
        const int c = it * 8 + wp;
        __stcs(obase + (long)c * 65536 + l, s[c * 33 + l]);
    }
}

extern "C" void kernel_launch(void* const* d_in, const int* in_sizes, int n_in,
                              void* d_out, int out_size) {
    const float* dist = (const float*)d_in[0];
    const float* zbuf = (const float*)d_in[1];
    const int*   pidx = (const int*)d_in[2];
    const float* feat = (const float*)d_in[3];
    float* out = (float*)d_out;

    const int nPix = 8 * 256 * 256;       // 524288
    rast_blend_kernel<<<nPix / 32, 256>>>(dist, zbuf, pidx, feat, out);
}